// round 17
// baseline (speedup 1.0000x reference)
#include <cuda_runtime.h>
#include <cstdint>

#define BB   256
#define IN   1024
#define OUTN 1024

#define OT 32    // out-cols per block (lane dimension)
#define BT 8     // batch rows per block (4 row-pairs)
#define IC 64    // i-chunk
#define NBUF 3   // triple buffer
#define NCHUNK (IN / IC)
#define NIG    (IC / 4)   // 16 ig groups (4 i's each) per chunk

// __device__ scratch (no allocation)
__device__ float g_WT4[(IN / 4) * OUTN * 4];      // [i/4][o][4]

typedef unsigned long long ull;

__device__ __forceinline__ float tanh_fast(float x) {
    float y;
    asm("tanh.approx.f32 %0, %1;" : "=f"(y) : "f"(x));
    return y;
}

// ---- Blackwell packed f32x2 ops (PTX-only) ----
__device__ __forceinline__ ull pack2(float lo, float hi) {
    ull r; asm("mov.b64 %0, {%1, %2};" : "=l"(r) : "f"(lo), "f"(hi)); return r;
}
__device__ __forceinline__ ull dup2(float v) {
    ull r; asm("mov.b64 %0, {%1, %1};" : "=l"(r) : "f"(v)); return r;
}
__device__ __forceinline__ void unpack2(ull v, float& lo, float& hi) {
    asm("mov.b64 {%0, %1}, %2;" : "=f"(lo), "=f"(hi) : "l"(v));
}
__device__ __forceinline__ ull mul2(ull a, ull b) {
    ull d; asm("mul.rn.f32x2 %0, %1, %2;" : "=l"(d) : "l"(a), "l"(b)); return d;
}
__device__ __forceinline__ ull add2(ull a, ull b) {
    ull d; asm("add.rn.f32x2 %0, %1, %2;" : "=l"(d) : "l"(a), "l"(b)); return d;
}
__device__ __forceinline__ ull fma2p(ull a, ull b, ull c) {
    ull d; asm("fma.rn.f32x2 %0, %1, %2, %3;" : "=l"(d) : "l"(a), "l"(b), "l"(c)); return d;
}

// ---- cp.async 16B ----
__device__ __forceinline__ void cp16(uint32_t dst_smem, const void* src) {
    asm volatile("cp.async.cg.shared.global [%0], [%1], 16;"
                 :: "r"(dst_smem), "l"(src));
}
__device__ __forceinline__ void cp_commit() {
    asm volatile("cp.async.commit_group;" ::: "memory");
}
template <int N> __device__ __forceinline__ void cp_wait() {
    asm volatile("cp.async.wait_group %0;" :: "n"(N) : "memory");
}

// ---------------------------------------------------------------------------
// Prep kernel: W_eff -> 4-wide interleaved g_WT4[i/4][o][4]. grid (32, 16).
// 64o x 32i tiles (the R15 config that measured fastest), MLP 8.
// ---------------------------------------------------------------------------
__global__ __launch_bounds__(256) void prep_kernel(
    const float* __restrict__ W,
    const float* __restrict__ fl)
{
    __shared__ float tile[64][37];
    const int itile = blockIdx.x * 32;
    const int otile = blockIdx.y * 64;
    const int o0 = threadIdx.x >> 3;          // 0..31
    const int cg = (threadIdx.x & 7) * 4;     // i-group

    int idxA = (otile + o0     ) * IN + itile + cg;
    int idxB = (otile + o0 + 32) * IN + itile + cg;
    float4 wA = *reinterpret_cast<const float4*>(&W[idxA]);
    float4 wB = *reinterpret_cast<const float4*>(&W[idxB]);
    float4 fA0 = *reinterpret_cast<const float4*>(&fl[3 * idxA + 0]);
    float4 fA1 = *reinterpret_cast<const float4*>(&fl[3 * idxA + 4]);
    float4 fA2 = *reinterpret_cast<const float4*>(&fl[3 * idxA + 8]);
    float4 fB0 = *reinterpret_cast<const float4*>(&fl[3 * idxB + 0]);
    float4 fB1 = *reinterpret_cast<const float4*>(&fl[3 * idxB + 4]);
    float4 fB2 = *reinterpret_cast<const float4*>(&fl[3 * idxB + 8]);

    float wa[8]  = {wA.x, wA.y, wA.z, wA.w, wB.x, wB.y, wB.z, wB.w};
    float la[24] = {fA0.x, fA0.y, fA0.z, fA0.w, fA1.x, fA1.y, fA1.z, fA1.w,
                    fA2.x, fA2.y, fA2.z, fA2.w,
                    fB0.x, fB0.y, fB0.z, fB0.w, fB1.x, fB1.y, fB1.z, fB1.w,
                    fB2.x, fB2.y, fB2.z, fB2.w};

    #pragma unroll
    for (int r = 0; r < 2; r++) {
        int o = o0 + r * 32;
        #pragma unroll
        for (int j = 0; j < 4; j++) {
            float w  = wa[r * 4 + j];
            float l0 = la[r * 12 + 3 * j + 0];
            float l1 = la[r * 12 + 3 * j + 1];
            float l2 = la[r * 12 + 3 * j + 2];
            float m  = fmaxf(l0, fmaxf(l1, l2));
            float e0 = __expf(l0 - m);
            float e1 = __expf(l1 - m);
            float e2 = __expf(l2 - m);
            float inv = 1.0f / (e0 + e1 + e2);
            float t = tanh_fast(w);
            float s = __sinf(w);
            tile[o][cg + j] = (e0 * w + e1 * t + e2 * s) * inv;
        }
    }
    __syncthreads();

    // write-out: 64 o x 8 ig = 512 float4 stores / 256 threads = 2 each
    const int tc = threadIdx.x & 63;      // o within tile
    const int tr = threadIdx.x >> 6;      // 0..3
    #pragma unroll
    for (int k = 0; k < 2; k++) {
        int ig = tr + 4 * k;              // 0..7 local ig
        float4 v;
        v.x = tile[tc][ig * 4 + 0];       // lane-stride 37 words: conflict-free
        v.y = tile[tc][ig * 4 + 1];
        v.z = tile[tc][ig * 4 + 2];
        v.w = tile[tc][ig * 4 + 3];
        *reinterpret_cast<float4*>(
            &g_WT4[((itile >> 2) + ig) * (OUTN * 4) + (otile + tc) * 4]) = v;
    }
}

// ---------------------------------------------------------------------------
// Kernel 2: out[b,o] = sum_i tanh(h[b,i] * W_eff[o,i]) + bias[o]
// R17: 256 threads / 8 warps, warp-specialized:
//   g = warp&3  -> batch row pair (2g, 2g+1)
//   P = warp>>2 -> ig-half [8P, 8P+8) of each chunk
// -> 55 warps/SM (14/SMSP, 2x R16) to close the latency-realization gap.
// w operand: LDS.128 of g_WT4 tile (4 i's, shared across both rows);
// h operand: LDS.128 broadcast.  Hybrid 7:9 deg-5 split with COMPILE-TIME
// pattern on local k (no branches).  Cross-P merge via smem reduction
// reusing the dead tile buffers.
// ---------------------------------------------------------------------------
__global__ __launch_bounds__(256, 7) void qfbn_main_kernel(
    const float* __restrict__ h,
    const float* __restrict__ bias,
    float* __restrict__ out)
{
    __shared__ __align__(16) float ws4[NBUF][NIG][OT][4];   // [buf][ig][o][4]
    __shared__ __align__(16) float hs[NBUF][BT][IC];        // row-major h tile

    const int tid   = threadIdx.x;
    const int lane  = tid & 31;
    const int warp  = tid >> 5;               // 0..7
    const int g     = warp & 3;               // row pair
    const int P     = warp >> 2;              // ig half
    const int rA    = 2 * g;
    const int rB    = 2 * g + 1;
    const int otile = blockIdx.x * OT;
    const int btile = blockIdx.y * BT;

    // deg-5 minimax-ish odd tanh on [0, 0.7]
    const ull C3_2 = dup2(-0.33270f);
    const ull C5_2 = dup2( 0.12620f);
    const ull ONE2 = dup2( 1.0f);

    ull accMA = 0, accMB = 0;   // MUFU-path packed accumulators
    ull accPA = 0, accPB = 0;   // poly-path

    auto prefetch = [&](int buf, int c) {
        const int ibase = c * IC;
        // W tile: 16 igs x 32 o x 16B = 512 cells / 256 threads = 2 each
        #pragma unroll
        for (int k = 0; k < 2; k++) {
            int q  = tid + k * 256;
            int ig = q >> 5;
            int o  = q & 31;
            uint32_t dst = (uint32_t)__cvta_generic_to_shared(&ws4[buf][ig][o][0]);
            cp16(dst, &g_WT4[((ibase >> 2) + ig) * (OUTN * 4) + (otile + o) * 4]);
        }
        // h tile: 8 rows x 64 f = 128 cells (tid < 128)
        if (tid < 128) {
            int r = tid >> 4;
            int q = tid & 15;
            uint32_t dst = (uint32_t)__cvta_generic_to_shared(&hs[buf][r][q * 4]);
            cp16(dst, &h[(btile + r) * IN + ibase + q * 4]);
        }
        cp_commit();
    };

    prefetch(0, 0);
    prefetch(1, 1);

    int buf = 0;
    for (int c = 0; c < NCHUNK; c++) {
        if (c + 1 < NCHUNK) cp_wait<1>();
        else                cp_wait<0>();
        __syncthreads();
        if (c + 2 < NCHUNK) {
            int nbuf = buf + 2; if (nbuf >= NBUF) nbuf -= NBUF;
            prefetch(nbuf, c + 2);
        }

        const int igbase = 8 * P;            // runtime half-offset
        #pragma unroll
        for (int k = 0; k < 8; k++) {        // compile-time k -> branch-free
            int ig = igbase + k;
            // w: 4 i's for this lane's o (LDS.128, conflict-free)
            ulonglong2 wv = *reinterpret_cast<const ulonglong2*>(&ws4[buf][ig][lane][0]);
            // h: 4 i's per row (LDS.128 broadcast)
            ulonglong2 ha = *reinterpret_cast<const ulonglong2*>(&hs[buf][rA][ig * 4]);
            ulonglong2 hb = *reinterpret_cast<const ulonglong2*>(&hs[buf][rB][ig * 4]);

            ull zA0 = mul2(ha.x, wv.x);   // i-pair (4ig, 4ig+1)
            ull zA1 = mul2(ha.y, wv.y);   // i-pair (4ig+2, 4ig+3)
            ull zB0 = mul2(hb.x, wv.x);
            ull zB1 = mul2(hb.y, wv.y);

            // pattern (compile-time): pair0 MUFU at k in {0,3,6},
            //                         pair1 MUFU at k in {1,4,5,7}  -> 7:9
            const bool mu0 = (k == 0 || k == 3 || k == 6);
            const bool mu1 = (k == 1 || k == 4 || k == 5 || k == 7);

            if (mu0) {
                float x0, x1, y0, y1;
                unpack2(zA0, x0, x1);
                unpack2(zB0, y0, y1);
                accMA = add2(accMA, pack2(tanh_fast(x0), tanh_fast(x1)));
                accMB = add2(accMB, pack2(tanh_fast(y0), tanh_fast(y1)));
            } else {
                ull uA = mul2(zA0, zA0);
                ull uB = mul2(zB0, zB0);
                ull qA = fma2p(uA, C5_2, C3_2);
                ull qB = fma2p(uB, C5_2, C3_2);
                ull rA2 = fma2p(qA, uA, ONE2);
                ull rB2 = fma2p(qB, uB, ONE2);
                accPA = fma2p(zA0, rA2, accPA);
                accPB = fma2p(zB0, rB2, accPB);
            }
            if (mu1) {
                float x0, x1, y0, y1;
                unpack2(zA1, x0, x1);
                unpack2(zB1, y0, y1);
                accMA = add2(accMA, pack2(tanh_fast(x0), tanh_fast(x1)));
                accMB = add2(accMB, pack2(tanh_fast(y0), tanh_fast(y1)));
            } else {
                ull uA = mul2(zA1, zA1);
                ull uB = mul2(zB1, zB1);
                ull qA = fma2p(uA, C5_2, C3_2);
                ull qB = fma2p(uB, C5_2, C3_2);
                ull rA2 = fma2p(qA, uA, ONE2);
                ull rB2 = fma2p(qB, uB, ONE2);
                accPA = fma2p(zA1, rA2, accPA);
                accPB = fma2p(zB1, rB2, accPB);
            }
        }

        if (++buf >= NBUF) buf = 0;
    }

    // Epilogue: merge P halves via smem (reuse dead ws4 buffers)
    ull sA = add2(accMA, accPA);
    ull sB = add2(accMB, accPB);
    ull* red = reinterpret_cast<ull*>(&ws4[0][0][0][0]);   // 4g x 2 x 32 ulls
    __syncthreads();                                       // all reads of bufs done
    if (P == 1) {
        red[(g * 2 + 0) * 32 + lane] = sA;
        red[(g * 2 + 1) * 32 + lane] = sB;
    }
    __syncthreads();
    if (P == 0) {
        ull tA = add2(sA, red[(g * 2 + 0) * 32 + lane]);
        ull tB = add2(sB, red[(g * 2 + 1) * 32 + lane]);
        float a0, a1, b0, b1;
        unpack2(tA, a0, a1);
        unpack2(tB, b0, b1);
        int o = otile + lane;
        float bv = bias[o];
        out[(btile + rA) * OUTN + o] = (a0 + a1) + bv;
        out[(btile + rB) * OUTN + o] = (b0 + b1) + bv;
    }
}

// ---------------------------------------------------------------------------
// Inputs (metadata order): h, W, b, f_logits. Output float (B, OUT).
// Graph-capturable: two kernel launches, no sync, no alloc.
// ---------------------------------------------------------------------------
extern "C" void kernel_launch(void* const* d_in, const int* in_sizes, int n_in,
                              void* d_out, int out_size)
{
    const float* h        = (const float*)d_in[0];
    const float* W        = (const float*)d_in[1];
    const float* bias     = (const float*)d_in[2];
    const float* f_logits = (const float*)d_in[3];
    float* out            = (float*)d_out;

    (void)in_sizes; (void)n_in; (void)out_size;

    dim3 pgrid(32, 16);
    prep_kernel<<<pgrid, 256>>>(W, f_logits);

    dim3 grid(OUTN / OT, BB / BT);   // 32 x 32 = 1024 blocks
    qfbn_main_kernel<<<grid, 256>>>(h, bias, out);
}